// round 13
// baseline (speedup 1.0000x reference)
#include <cuda_runtime.h>
#include <cuda_fp16.h>
#include <math.h>
#include <stdint.h>

#define B_   32768
#define H_   256
#define DK_  64
#define DV_  128
#define S_   8192
#define NA_  4096

// ================= device scratch =================
__device__ float    g_qs  [(size_t)B_ * DK_];   // q * invnorm / TEMP
__device__ __half   g_kh  [(size_t)NA_ * DK_];  // k-hat hi   [slot][dk]
__device__ __half   g_kl  [(size_t)NA_ * DK_];  // k-hat lo residual
__device__ __half   g_vhT [(size_t)DV_ * NA_];  // V^T        [dv][slot]
__device__ uint32_t g_eh  [(size_t)B_ * 2048];  // unnorm exp(sims) as half2
__device__ float    g_invl[B_];
__device__ float    g_colsum[NA_];

__device__ __forceinline__ int idx_mode(const void* a) {
    const long long* a64 = (const long long*)a;
    long long v0 = a64[0], v1 = a64[1];
    return (v0 >= 0 && v0 < S_ && v1 >= 0 && v1 < S_) ? 1 : 0;
}
__device__ __forceinline__ int load_idx(const void* a, int i, int mode) {
    return mode ? (int)((const long long*)a)[i] : ((const int*)a)[i];
}

// FFMA-pipe exp: valid for |x| <= ~40, rel err ~1e-7. No MUFU.
__device__ __forceinline__ float fast_exp(float x) {
    float y = x * 1.4426950408889634f;
    float t = y + 12582912.0f;
    int   n = __float_as_int(t) - 0x4B400000;
    float f = y - (t - 12582912.0f);
    float p = 1.5403530e-4f;
    p = fmaf(p, f, 1.3333558e-3f);
    p = fmaf(p, f, 9.6181291e-3f);
    p = fmaf(p, f, 5.5504109e-2f);
    p = fmaf(p, f, 2.4022651e-1f);
    p = fmaf(p, f, 6.9314718e-1f);
    p = fmaf(p, f, 1.0f);
    return p * __int_as_float((n + 127) << 23);
}

__device__ __forceinline__ uint32_t smem_to_u32(const void* p) {
    uint32_t a;
    asm("{ .reg .u64 t; cvta.to.shared.u64 t, %1; cvt.u32.u64 %0, t; }" : "=r"(a) : "l"(p));
    return a;
}
__device__ __forceinline__ void cp16(uint32_t smem, const void* g) {
    asm volatile("cp.async.cg.shared.global [%0], [%1], 16;" :: "r"(smem), "l"(g));
}

__device__ __forceinline__ uint32_t pack_split_h(float a, float b, uint32_t& lo) {
    __half2 hh = __floats2half2_rn(a, b);
    float2 hf = __half22float2(hh);
    __half2 ll = __floats2half2_rn(a - hf.x, b - hf.y);
    lo = *(uint32_t*)&ll;
    return *(uint32_t*)&hh;
}
__device__ __forceinline__ uint32_t pack_h(float a, float b) {
    __half2 hh = __floats2half2_rn(a, b);
    return *(uint32_t*)&hh;
}

__device__ __forceinline__ void mma16816(float* c, const uint32_t* a,
                                         uint32_t b0, uint32_t b1) {
    asm volatile("mma.sync.aligned.m16n8k16.row.col.f32.f16.f16.f32 "
                 "{%0,%1,%2,%3}, {%4,%5,%6,%7}, {%8,%9}, {%0,%1,%2,%3};"
                 : "+f"(c[0]), "+f"(c[1]), "+f"(c[2]), "+f"(c[3])
                 : "r"(a[0]), "r"(a[1]), "r"(a[2]), "r"(a[3]), "r"(b0), "r"(b1));
}

// ---- K1: query = hidden @ kw^T ; g_qs = q*invnorm/TEMP ----
#define QPROJ_SMEM ((16384 + 16384 + 64) * 4)
__global__ __launch_bounds__(256) void k_qproj(const float* __restrict__ hidden,
                                               const float* __restrict__ kw,
                                               float* __restrict__ out_q) {
    extern __shared__ float sm1[];
    float* hid_s = sm1;
    float* kwT   = sm1 + 16384;
    float* inv_s = sm1 + 32768;
    const int tid = threadIdx.x;
    const int rowbase = blockIdx.x * 64;
    #pragma unroll
    for (int i = 0; i < 16; ++i) {
        int id = tid + i * 256, r = id >> 6, c4 = id & 63;
        *(float4*)&hid_s[r * 256 + c4 * 4] =
            *(const float4*)&hidden[(size_t)(rowbase + r) * 256 + c4 * 4];
    }
    #pragma unroll
    for (int i = 0; i < 16; ++i) {
        int id = tid + i * 256, c = id & 63, k4 = id >> 6;
        float4 v = *(const float4*)&kw[(size_t)c * 256 + k4 * 4];
        kwT[(k4 * 4 + 0) * 64 + c] = v.x; kwT[(k4 * 4 + 1) * 64 + c] = v.y;
        kwT[(k4 * 4 + 2) * 64 + c] = v.z; kwT[(k4 * 4 + 3) * 64 + c] = v.w;
    }
    __syncthreads();
    const int tx = tid & 15, ty = tid >> 4;
    float acc[4][4] = {};
    #pragma unroll 4
    for (int k = 0; k < 256; ++k) {
        float4 b = *(float4*)&kwT[k * 64 + tx * 4];
        #pragma unroll
        for (int i = 0; i < 4; ++i) {
            float a = hid_s[(ty * 4 + i) * 256 + k];
            acc[i][0] += a * b.x; acc[i][1] += a * b.y;
            acc[i][2] += a * b.z; acc[i][3] += a * b.w;
        }
    }
    __syncthreads();
    float* q_s = hid_s;
    #pragma unroll
    for (int i = 0; i < 4; ++i)
        *(float4*)&q_s[(ty * 4 + i) * 68 + tx * 4] =
            make_float4(acc[i][0], acc[i][1], acc[i][2], acc[i][3]);
    __syncthreads();
    if (tid < 64) {
        float ss = 0.f;
        #pragma unroll
        for (int c4 = 0; c4 < 16; ++c4) {
            float4 v = *(float4*)&q_s[tid * 68 + c4 * 4];
            ss += v.x * v.x + v.y * v.y + v.z * v.z + v.w * v.w;
        }
        inv_s[tid] = 1.0f / fmaxf(sqrtf(ss), 1e-12f);
    }
    __syncthreads();
    #pragma unroll
    for (int i = 0; i < 4; ++i) {
        int r = ty * 4 + i;
        float4 v = make_float4(acc[i][0], acc[i][1], acc[i][2], acc[i][3]);
        *(float4*)&out_q[(size_t)(rowbase + r) * 64 + tx * 4] = v;
        float s = inv_s[r] * 10.0f;
        *(float4*)&g_qs[(size_t)(rowbase + r) * 64 + tx * 4] =
            make_float4(v.x * s, v.y * s, v.z * s, v.w * s);
    }
}

// ---- K2: normalize keys (fp16 split), transpose values (fp16) ----
__global__ __launch_bounds__(64) void k_prep(const float* __restrict__ slots_key,
                                             const float* __restrict__ slots_value,
                                             const void* __restrict__ active_idx) {
    const int i = blockIdx.x, t = threadIdx.x;
    const int mode = idx_mode(active_idx);
    const int idx = load_idx(active_idx, i, mode);
    float v = slots_key[(size_t)idx * DK_ + t];
    float ss = v * v;
    #pragma unroll
    for (int o = 16; o > 0; o >>= 1) ss += __shfl_down_sync(0xffffffffu, ss, o);
    __shared__ float sred[2];
    if ((t & 31) == 0) sred[t >> 5] = ss;
    __syncthreads();
    float inv = 1.0f / fmaxf(sqrtf(sred[0] + sred[1]), 1e-12f);
    float kn = v * inv;
    __half kh = __float2half_rn(kn);
    g_kh[(size_t)i * DK_ + t] = kh;
    g_kl[(size_t)i * DK_ + t] = __float2half_rn(kn - __half2float(kh));
    #pragma unroll
    for (int h = 0; h < 2; ++h) {
        int d = t + h * 64;
        g_vhT[(size_t)d * NA_ + i] = __float2half_rn(slots_value[(size_t)idx * DV_ + d]);
    }
    if (t == 0) g_colsum[i] = 0.f;
}

// ---- K3: HMMA fused attention (round-7 core; attn -> fp16 scratch), chunked ----
#define BUF_SZ  71680
#define KL_OFF  18432
#define VH_OFF  36864
#define MMA_SMEM (2 * BUF_SZ)

__global__ __launch_bounds__(256, 1) void k_attn_mma(float* __restrict__ out_ctx,
                                                     int row0) {
    extern __shared__ char smc[];
    const uint32_t sbase = smem_to_u32(smc);
    const int tid  = threadIdx.x;
    const int wid  = tid >> 5, lane = tid & 31;
    const int g    = lane >> 2, tg = lane & 3;
    const int rowbase = row0 + blockIdx.x * 128;
    const int r0 = rowbase + wid * 16 + g;
    const int r1 = r0 + 8;

    uint32_t qh[4][4], ql[4][4];
    {
        const float* q0 = g_qs + (size_t)r0 * 64;
        const float* q1 = g_qs + (size_t)r1 * 64;
        #pragma unroll
        for (int kk = 0; kk < 4; ++kk) {
            int c = kk * 16 + tg * 2;
            float2 v00 = *(const float2*)(q0 + c);
            float2 v10 = *(const float2*)(q1 + c);
            float2 v01 = *(const float2*)(q0 + c + 8);
            float2 v11 = *(const float2*)(q1 + c + 8);
            qh[kk][0] = pack_split_h(v00.x, v00.y, ql[kk][0]);
            qh[kk][1] = pack_split_h(v10.x, v10.y, ql[kk][1]);
            qh[kk][2] = pack_split_h(v01.x, v01.y, ql[kk][2]);
            qh[kk][3] = pack_split_h(v11.x, v11.y, ql[kk][3]);
        }
    }

    float ctxa[64];
    #pragma unroll
    for (int i = 0; i < 64; ++i) ctxa[i] = 0.f;
    float rs0 = 0.f, rs1 = 0.f;

    auto load_tile = [&](int t, int b) {
        const int cb = t * 128;
        const uint32_t bb = sbase + b * BUF_SZ;
        #pragma unroll
        for (int i = 0; i < 4; ++i) {
            int id = tid + i * 256, row = id >> 3, c = id & 7;
            cp16(bb + row * 144 + c * 16, g_kh + (size_t)(cb + row) * 64 + c * 8);
        }
        #pragma unroll
        for (int i = 0; i < 4; ++i) {
            int id = tid + i * 256, row = id >> 3, c = id & 7;
            cp16(bb + KL_OFF + row * 144 + c * 16, g_kl + (size_t)(cb + row) * 64 + c * 8);
        }
        #pragma unroll
        for (int i = 0; i < 8; ++i) {
            int id = tid + i * 256, row = id >> 4, c = id & 15;
            cp16(bb + VH_OFF + row * 272 + c * 16, g_vhT + (size_t)row * NA_ + cb + c * 8);
        }
        asm volatile("cp.async.commit_group;" ::: "memory");
    };

    load_tile(0, 0);

    const char* kh_l0 = smc + (size_t)(g * 144 + tg * 4);
    const char* kl_l0 = smc + (size_t)(KL_OFF + g * 144 + tg * 4);
    const char* vh_l0 = smc + (size_t)(VH_OFF + g * 272 + tg * 4);

    #pragma unroll 1
    for (int t = 0; t < 32; ++t) {
        const int cb = t * 128;
        __syncthreads();
        if (t < 31) load_tile(t + 1, (t + 1) & 1);
        if (t < 31) asm volatile("cp.async.wait_group 1;" ::: "memory");
        else        asm volatile("cp.async.wait_group 0;" ::: "memory");
        __syncthreads();

        const size_t boff = (size_t)(t & 1) * BUF_SZ;
        const char* kh_l = kh_l0 + boff;
        const char* kl_l = kl_l0 + boff;
        const char* vh_l = vh_l0 + boff;

        uint32_t ph[8][4];
        #pragma unroll
        for (int n = 0; n < 16; ++n) {
            float ccA[4] = {0.f, 0.f, 0.f, 0.f};
            float ccB[4] = {0.f, 0.f, 0.f, 0.f};
            float ccC[4] = {0.f, 0.f, 0.f, 0.f};
            const char* kh_n = kh_l + n * (8 * 144);
            const char* kl_n = kl_l + n * (8 * 144);
            #pragma unroll
            for (int kk = 0; kk < 4; ++kk) {
                uint32_t bh0 = *(const uint32_t*)(kh_n + kk * 32);
                uint32_t bh1 = *(const uint32_t*)(kh_n + kk * 32 + 16);
                uint32_t bl0 = *(const uint32_t*)(kl_n + kk * 32);
                uint32_t bl1 = *(const uint32_t*)(kl_n + kk * 32 + 16);
                mma16816(ccA, qh[kk], bh0, bh1);
                mma16816(ccB, ql[kk], bh0, bh1);
                mma16816(ccC, qh[kk], bl0, bl1);
            }
            float e0 = fast_exp(ccA[0] + ccB[0] + ccC[0]);
            float e1 = fast_exp(ccA[1] + ccB[1] + ccC[1]);
            float e2 = fast_exp(ccA[2] + ccB[2] + ccC[2]);
            float e3 = fast_exp(ccA[3] + ccB[3] + ccC[3]);
            rs0 += e0 + e1; rs1 += e2 + e3;
            int j = n >> 1, h = (n & 1) * 2;
            uint32_t p01 = pack_h(e0, e1);
            uint32_t p23 = pack_h(e2, e3);
            ph[j][h]     = p01;
            ph[j][h + 1] = p23;
            int cidx = (cb >> 1) + n * 4 + tg;
            g_eh[(size_t)r0 * 2048 + cidx] = p01;
            g_eh[(size_t)r1 * 2048 + cidx] = p23;
        }

        #pragma unroll
        for (int kk = 0; kk < 8; ++kk) {
            const char* vh_k = vh_l + kk * 32;
            #pragma unroll
            for (int n = 0; n < 16; ++n) {
                uint32_t bh0 = *(const uint32_t*)(vh_k + n * (8 * 272));
                uint32_t bh1 = *(const uint32_t*)(vh_k + n * (8 * 272) + 16);
                mma16816(ctxa + n * 4, ph[kk], bh0, bh1);
            }
        }
    }

    rs0 += __shfl_xor_sync(0xffffffffu, rs0, 1);
    rs0 += __shfl_xor_sync(0xffffffffu, rs0, 2);
    rs1 += __shfl_xor_sync(0xffffffffu, rs1, 1);
    rs1 += __shfl_xor_sync(0xffffffffu, rs1, 2);
    float i0 = 1.f / rs0, i1 = 1.f / rs1;
    if (tg == 0) { g_invl[r0] = i0; g_invl[r1] = i1; }
    #pragma unroll
    for (int n = 0; n < 16; ++n) {
        int colb = n * 8 + tg * 2;
        __stcs((float2*)(out_ctx + (size_t)r0 * 128 + colb),
               make_float2(ctxa[n * 4] * i0, ctxa[n * 4 + 1] * i0));
        __stcs((float2*)(out_ctx + (size_t)r1 * 128 + colb),
               make_float2(ctxa[n * 4 + 2] * i1, ctxa[n * 4 + 3] * i1));
    }
}

// ---- K4: read fp16 scratch, normalize -> fp32 attn + column sums (chunked) ----
__global__ __launch_bounds__(256) void k_norm(float* __restrict__ attn, int rb0) {
    __shared__ float invl_s[64];
    const int tid = threadIdx.x;
    const int rb = rb0 + blockIdx.x * 64;
    if (tid < 64) invl_s[tid] = g_invl[rb + tid];
    __syncthreads();
    float cs[16];
    #pragma unroll
    for (int j = 0; j < 16; ++j) cs[j] = 0.f;
    #pragma unroll 1
    for (int r = 0; r < 64; ++r) {
        float iv = invl_s[r];
        const uint4* src = (const uint4*)(g_eh + (size_t)(rb + r) * 2048);
        float4* dst = (float4*)(attn + (size_t)(rb + r) * 4096);
        #pragma unroll
        for (int j = 0; j < 2; ++j) {
            uint4 u = __ldcs(&src[tid + j * 256]);
            float2 f0 = __half22float2(*(__half2*)&u.x);
            float2 f1 = __half22float2(*(__half2*)&u.y);
            float2 f2 = __half22float2(*(__half2*)&u.z);
            float2 f3 = __half22float2(*(__half2*)&u.w);
            float4 v0 = make_float4(f0.x * iv, f0.y * iv, f1.x * iv, f1.y * iv);
            float4 v1 = make_float4(f2.x * iv, f2.y * iv, f3.x * iv, f3.y * iv);
            __stcs(&dst[(tid + j * 256) * 2 + 0], v0);
            __stcs(&dst[(tid + j * 256) * 2 + 1], v1);
            cs[j * 8 + 0] += v0.x; cs[j * 8 + 1] += v0.y;
            cs[j * 8 + 2] += v0.z; cs[j * 8 + 3] += v0.w;
            cs[j * 8 + 4] += v1.x; cs[j * 8 + 5] += v1.y;
            cs[j * 8 + 6] += v1.z; cs[j * 8 + 7] += v1.w;
        }
    }
    #pragma unroll
    for (int j = 0; j < 2; ++j) {
        int c = (tid + j * 256) * 8;
        #pragma unroll
        for (int m = 0; m < 8; ++m)
            atomicAdd(&g_colsum[c + m], cs[j * 8 + m]);
    }
}

// ---- K5: usage EMA ----
__global__ void k_usage_copy(const float* __restrict__ ue, float* __restrict__ out) {
    int i = blockIdx.x * 256 + threadIdx.x;
    if (i < S_) out[i] = ue[i];
}
__global__ void k_usage_scatter(const float* __restrict__ ue,
                                const void* __restrict__ aidx,
                                float* __restrict__ out) {
    int i = blockIdx.x * 256 + threadIdx.x;
    if (i < NA_) {
        int mode = idx_mode(aidx);
        int idx = load_idx(aidx, i, mode);
        out[idx] = 0.95f * ue[idx] + 0.05f * (g_colsum[i] * (1.0f / 32768.0f));
    }
}

extern "C" void kernel_launch(void* const* d_in, const int* in_sizes, int n_in,
                              void* d_out, int out_size) {
    const float* hidden = (const float*)d_in[0];
    const float* kw     = (const float*)d_in[1];
    const float* skey   = (const float*)d_in[2];
    const float* sval   = (const float*)d_in[3];
    const float* uema   = (const float*)d_in[4];
    const void*  aidx   = d_in[5];

    float* out    = (float*)d_out;
    float* o_ctx  = out;
    float* o_attn = out + (size_t)4194304;
    float* o_q    = out + (size_t)138412032;
    float* o_use  = out + (size_t)140509184;

    static cudaStream_t s1 = nullptr;
    static cudaEvent_t evF, evP, evA0, evA1, evN;
    if (!s1) {
        cudaStreamCreateWithFlags(&s1, cudaStreamNonBlocking);
        cudaEventCreateWithFlags(&evF,  cudaEventDisableTiming);
        cudaEventCreateWithFlags(&evP,  cudaEventDisableTiming);
        cudaEventCreateWithFlags(&evA0, cudaEventDisableTiming);
        cudaEventCreateWithFlags(&evA1, cudaEventDisableTiming);
        cudaEventCreateWithFlags(&evN,  cudaEventDisableTiming);
        cudaFuncSetAttribute(k_qproj,    cudaFuncAttributeMaxDynamicSharedMemorySize, QPROJ_SMEM);
        cudaFuncSetAttribute(k_attn_mma, cudaFuncAttributeMaxDynamicSharedMemorySize, MMA_SMEM);
    }

    // fork side stream from the (captured) main stream
    cudaEventRecord(evF, 0);
    cudaStreamWaitEvent(s1, evF, 0);

    // main: qproj ; side: prep + usage_copy (independent)
    k_qproj<<<B_ / 64, 256, QPROJ_SMEM>>>(hidden, kw, o_q);
    k_prep<<<NA_, 64, 0, s1>>>(skey, sval, aidx);
    k_usage_copy<<<(S_ + 255) / 256, 256, 0, s1>>>(uema, o_use);
    cudaEventRecord(evP, s1);
    cudaStreamWaitEvent(0, evP, 0);    // attn needs prep

    // attn chunk 0 (rows 0..16383)
    k_attn_mma<<<128, 256, MMA_SMEM>>>(o_ctx, 0);
    cudaEventRecord(evA0, 0);
    // attn chunk 1 (rows 16384..32767) — overlaps norm chunk 0 on s1
    k_attn_mma<<<128, 256, MMA_SMEM>>>(o_ctx, 16384);
    cudaEventRecord(evA1, 0);

    cudaStreamWaitEvent(s1, evA0, 0);
    k_norm<<<256, 256, 0, s1>>>(o_attn, 0);
    cudaStreamWaitEvent(s1, evA1, 0);
    k_norm<<<256, 256, 0, s1>>>(o_attn, 16384);
    cudaEventRecord(evN, s1);

    // rejoin: usage_scatter needs all colsums
    cudaStreamWaitEvent(0, evN, 0);
    k_usage_scatter<<<(NA_ + 255) / 256, 256>>>(uema, aidx, o_use);
}

// round 14
// speedup vs baseline: 1.2559x; 1.2559x over previous
#include <cuda_runtime.h>
#include <cuda_fp16.h>
#include <math.h>
#include <stdint.h>

#define B_   32768
#define H_   256
#define DK_  64
#define DV_  128
#define S_   8192
#define NA_  4096

// ================= device scratch =================
__device__ float    g_qs  [(size_t)B_ * DK_];   // q * invnorm / TEMP
__device__ __half   g_kh  [(size_t)NA_ * DK_];  // k-hat hi   [slot][dk]
__device__ __half   g_kl  [(size_t)NA_ * DK_];  // k-hat lo residual
__device__ __half   g_vhT [(size_t)DV_ * NA_];  // V^T        [dv][slot]
__device__ uint32_t g_eh  [(size_t)B_ * 2048];  // unnorm exp(sims) as half2
__device__ float    g_invl[B_];
__device__ float    g_colsum[NA_];

__device__ __forceinline__ int idx_mode(const void* a) {
    const long long* a64 = (const long long*)a;
    long long v0 = a64[0], v1 = a64[1];
    return (v0 >= 0 && v0 < S_ && v1 >= 0 && v1 < S_) ? 1 : 0;
}
__device__ __forceinline__ int load_idx(const void* a, int i, int mode) {
    return mode ? (int)((const long long*)a)[i] : ((const int*)a)[i];
}

// FFMA-pipe exp: valid for |x| <= ~40, rel err ~1e-7. No MUFU.
__device__ __forceinline__ float fast_exp(float x) {
    float y = x * 1.4426950408889634f;
    float t = y + 12582912.0f;
    int   n = __float_as_int(t) - 0x4B400000;
    float f = y - (t - 12582912.0f);
    float p = 1.5403530e-4f;
    p = fmaf(p, f, 1.3333558e-3f);
    p = fmaf(p, f, 9.6181291e-3f);
    p = fmaf(p, f, 5.5504109e-2f);
    p = fmaf(p, f, 2.4022651e-1f);
    p = fmaf(p, f, 6.9314718e-1f);
    p = fmaf(p, f, 1.0f);
    return p * __int_as_float((n + 127) << 23);
}

__device__ __forceinline__ uint32_t smem_to_u32(const void* p) {
    uint32_t a;
    asm("{ .reg .u64 t; cvta.to.shared.u64 t, %1; cvt.u32.u64 %0, t; }" : "=r"(a) : "l"(p));
    return a;
}
__device__ __forceinline__ void cp16(uint32_t smem, const void* g) {
    asm volatile("cp.async.cg.shared.global [%0], [%1], 16;" :: "r"(smem), "l"(g));
}

__device__ __forceinline__ uint32_t pack_split_h(float a, float b, uint32_t& lo) {
    __half2 hh = __floats2half2_rn(a, b);
    float2 hf = __half22float2(hh);
    __half2 ll = __floats2half2_rn(a - hf.x, b - hf.y);
    lo = *(uint32_t*)&ll;
    return *(uint32_t*)&hh;
}
__device__ __forceinline__ uint32_t pack_h(float a, float b) {
    __half2 hh = __floats2half2_rn(a, b);
    return *(uint32_t*)&hh;
}

__device__ __forceinline__ void mma16816(float* c, const uint32_t* a,
                                         uint32_t b0, uint32_t b1) {
    asm volatile("mma.sync.aligned.m16n8k16.row.col.f32.f16.f16.f32 "
                 "{%0,%1,%2,%3}, {%4,%5,%6,%7}, {%8,%9}, {%0,%1,%2,%3};"
                 : "+f"(c[0]), "+f"(c[1]), "+f"(c[2]), "+f"(c[3])
                 : "r"(a[0]), "r"(a[1]), "r"(a[2]), "r"(a[3]), "r"(b0), "r"(b1));
}

// ---- K1: query = hidden @ kw^T ; g_qs = q*invnorm/TEMP ----
#define QPROJ_SMEM ((16384 + 16384 + 64) * 4)
__global__ __launch_bounds__(256) void k_qproj(const float* __restrict__ hidden,
                                               const float* __restrict__ kw,
                                               float* __restrict__ out_q) {
    extern __shared__ float sm1[];
    float* hid_s = sm1;
    float* kwT   = sm1 + 16384;
    float* inv_s = sm1 + 32768;
    const int tid = threadIdx.x;
    const int rowbase = blockIdx.x * 64;
    #pragma unroll
    for (int i = 0; i < 16; ++i) {
        int id = tid + i * 256, r = id >> 6, c4 = id & 63;
        *(float4*)&hid_s[r * 256 + c4 * 4] =
            *(const float4*)&hidden[(size_t)(rowbase + r) * 256 + c4 * 4];
    }
    #pragma unroll
    for (int i = 0; i < 16; ++i) {
        int id = tid + i * 256, c = id & 63, k4 = id >> 6;
        float4 v = *(const float4*)&kw[(size_t)c * 256 + k4 * 4];
        kwT[(k4 * 4 + 0) * 64 + c] = v.x; kwT[(k4 * 4 + 1) * 64 + c] = v.y;
        kwT[(k4 * 4 + 2) * 64 + c] = v.z; kwT[(k4 * 4 + 3) * 64 + c] = v.w;
    }
    __syncthreads();
    const int tx = tid & 15, ty = tid >> 4;
    float acc[4][4] = {};
    #pragma unroll 4
    for (int k = 0; k < 256; ++k) {
        float4 b = *(float4*)&kwT[k * 64 + tx * 4];
        #pragma unroll
        for (int i = 0; i < 4; ++i) {
            float a = hid_s[(ty * 4 + i) * 256 + k];
            acc[i][0] += a * b.x; acc[i][1] += a * b.y;
            acc[i][2] += a * b.z; acc[i][3] += a * b.w;
        }
    }
    __syncthreads();
    float* q_s = hid_s;
    #pragma unroll
    for (int i = 0; i < 4; ++i)
        *(float4*)&q_s[(ty * 4 + i) * 68 + tx * 4] =
            make_float4(acc[i][0], acc[i][1], acc[i][2], acc[i][3]);
    __syncthreads();
    if (tid < 64) {
        float ss = 0.f;
        #pragma unroll
        for (int c4 = 0; c4 < 16; ++c4) {
            float4 v = *(float4*)&q_s[tid * 68 + c4 * 4];
            ss += v.x * v.x + v.y * v.y + v.z * v.z + v.w * v.w;
        }
        inv_s[tid] = 1.0f / fmaxf(sqrtf(ss), 1e-12f);
    }
    __syncthreads();
    #pragma unroll
    for (int i = 0; i < 4; ++i) {
        int r = ty * 4 + i;
        float4 v = make_float4(acc[i][0], acc[i][1], acc[i][2], acc[i][3]);
        *(float4*)&out_q[(size_t)(rowbase + r) * 64 + tx * 4] = v;
        float s = inv_s[r] * 10.0f;
        *(float4*)&g_qs[(size_t)(rowbase + r) * 64 + tx * 4] =
            make_float4(v.x * s, v.y * s, v.z * s, v.w * s);
    }
}

// ---- K2: normalize keys (fp16 split), transpose values (fp16) ----
__global__ __launch_bounds__(64) void k_prep(const float* __restrict__ slots_key,
                                             const float* __restrict__ slots_value,
                                             const void* __restrict__ active_idx) {
    const int i = blockIdx.x, t = threadIdx.x;
    const int mode = idx_mode(active_idx);
    const int idx = load_idx(active_idx, i, mode);
    float v = slots_key[(size_t)idx * DK_ + t];
    float ss = v * v;
    #pragma unroll
    for (int o = 16; o > 0; o >>= 1) ss += __shfl_down_sync(0xffffffffu, ss, o);
    __shared__ float sred[2];
    if ((t & 31) == 0) sred[t >> 5] = ss;
    __syncthreads();
    float inv = 1.0f / fmaxf(sqrtf(sred[0] + sred[1]), 1e-12f);
    float kn = v * inv;
    __half kh = __float2half_rn(kn);
    g_kh[(size_t)i * DK_ + t] = kh;
    g_kl[(size_t)i * DK_ + t] = __float2half_rn(kn - __half2float(kh));
    #pragma unroll
    for (int h = 0; h < 2; ++h) {
        int d = t + h * 64;
        g_vhT[(size_t)d * NA_ + i] = __float2half_rn(slots_value[(size_t)idx * DV_ + d]);
    }
    if (t == 0) g_colsum[i] = 0.f;
}

// ---- K3: HMMA fused attention (round-7 core; attn -> fp16 scratch) ----
#define BUF_SZ  71680
#define KL_OFF  18432
#define VH_OFF  36864
#define MMA_SMEM (2 * BUF_SZ)

__global__ __launch_bounds__(256, 1) void k_attn_mma(float* __restrict__ out_ctx) {
    extern __shared__ char smc[];
    const uint32_t sbase = smem_to_u32(smc);
    const int tid  = threadIdx.x;
    const int wid  = tid >> 5, lane = tid & 31;
    const int g    = lane >> 2, tg = lane & 3;
    const int rowbase = blockIdx.x * 128;
    const int r0 = rowbase + wid * 16 + g;
    const int r1 = r0 + 8;

    uint32_t qh[4][4], ql[4][4];
    {
        const float* q0 = g_qs + (size_t)r0 * 64;
        const float* q1 = g_qs + (size_t)r1 * 64;
        #pragma unroll
        for (int kk = 0; kk < 4; ++kk) {
            int c = kk * 16 + tg * 2;
            float2 v00 = *(const float2*)(q0 + c);
            float2 v10 = *(const float2*)(q1 + c);
            float2 v01 = *(const float2*)(q0 + c + 8);
            float2 v11 = *(const float2*)(q1 + c + 8);
            qh[kk][0] = pack_split_h(v00.x, v00.y, ql[kk][0]);
            qh[kk][1] = pack_split_h(v10.x, v10.y, ql[kk][1]);
            qh[kk][2] = pack_split_h(v01.x, v01.y, ql[kk][2]);
            qh[kk][3] = pack_split_h(v11.x, v11.y, ql[kk][3]);
        }
    }

    float ctxa[64];
    #pragma unroll
    for (int i = 0; i < 64; ++i) ctxa[i] = 0.f;
    float rs0 = 0.f, rs1 = 0.f;

    auto load_tile = [&](int t, int b) {
        const int cb = t * 128;
        const uint32_t bb = sbase + b * BUF_SZ;
        #pragma unroll
        for (int i = 0; i < 4; ++i) {
            int id = tid + i * 256, row = id >> 3, c = id & 7;
            cp16(bb + row * 144 + c * 16, g_kh + (size_t)(cb + row) * 64 + c * 8);
        }
        #pragma unroll
        for (int i = 0; i < 4; ++i) {
            int id = tid + i * 256, row = id >> 3, c = id & 7;
            cp16(bb + KL_OFF + row * 144 + c * 16, g_kl + (size_t)(cb + row) * 64 + c * 8);
        }
        #pragma unroll
        for (int i = 0; i < 8; ++i) {
            int id = tid + i * 256, row = id >> 4, c = id & 15;
            cp16(bb + VH_OFF + row * 272 + c * 16, g_vhT + (size_t)row * NA_ + cb + c * 8);
        }
        asm volatile("cp.async.commit_group;" ::: "memory");
    };

    load_tile(0, 0);

    const char* kh_l0 = smc + (size_t)(g * 144 + tg * 4);
    const char* kl_l0 = smc + (size_t)(KL_OFF + g * 144 + tg * 4);
    const char* vh_l0 = smc + (size_t)(VH_OFF + g * 272 + tg * 4);

    #pragma unroll 1
    for (int t = 0; t < 32; ++t) {
        const int cb = t * 128;
        __syncthreads();
        if (t < 31) load_tile(t + 1, (t + 1) & 1);
        if (t < 31) asm volatile("cp.async.wait_group 1;" ::: "memory");
        else        asm volatile("cp.async.wait_group 0;" ::: "memory");
        __syncthreads();

        const size_t boff = (size_t)(t & 1) * BUF_SZ;
        const char* kh_l = kh_l0 + boff;
        const char* kl_l = kl_l0 + boff;
        const char* vh_l = vh_l0 + boff;

        // sims: qh*kh + ql*kh + qh*kl, 3 independent chains
        uint32_t ph[8][4];
        #pragma unroll
        for (int n = 0; n < 16; ++n) {
            float ccA[4] = {0.f, 0.f, 0.f, 0.f};
            float ccB[4] = {0.f, 0.f, 0.f, 0.f};
            float ccC[4] = {0.f, 0.f, 0.f, 0.f};
            const char* kh_n = kh_l + n * (8 * 144);
            const char* kl_n = kl_l + n * (8 * 144);
            #pragma unroll
            for (int kk = 0; kk < 4; ++kk) {
                uint32_t bh0 = *(const uint32_t*)(kh_n + kk * 32);
                uint32_t bh1 = *(const uint32_t*)(kh_n + kk * 32 + 16);
                uint32_t bl0 = *(const uint32_t*)(kl_n + kk * 32);
                uint32_t bl1 = *(const uint32_t*)(kl_n + kk * 32 + 16);
                mma16816(ccA, qh[kk], bh0, bh1);
                mma16816(ccB, ql[kk], bh0, bh1);
                mma16816(ccC, qh[kk], bl0, bl1);
            }
            float e0 = fast_exp(ccA[0] + ccB[0] + ccC[0]);
            float e1 = fast_exp(ccA[1] + ccB[1] + ccC[1]);
            float e2 = fast_exp(ccA[2] + ccB[2] + ccC[2]);
            float e3 = fast_exp(ccA[3] + ccB[3] + ccC[3]);
            rs0 += e0 + e1; rs1 += e2 + e3;
            int j = n >> 1, h = (n & 1) * 2;
            uint32_t p01 = pack_h(e0, e1);
            uint32_t p23 = pack_h(e2, e3);
            ph[j][h]     = p01;
            ph[j][h + 1] = p23;
            int cidx = (cb >> 1) + n * 4 + tg;
            g_eh[(size_t)r0 * 2048 + cidx] = p01;
            g_eh[(size_t)r1 * 2048 + cidx] = p23;
        }

        // ctx: ph * vh, kk-outer for 16 independent chains
        #pragma unroll
        for (int kk = 0; kk < 8; ++kk) {
            const char* vh_k = vh_l + kk * 32;
            #pragma unroll
            for (int n = 0; n < 16; ++n) {
                uint32_t bh0 = *(const uint32_t*)(vh_k + n * (8 * 272));
                uint32_t bh1 = *(const uint32_t*)(vh_k + n * (8 * 272) + 16);
                mma16816(ctxa + n * 4, ph[kk], bh0, bh1);
            }
        }
    }

    rs0 += __shfl_xor_sync(0xffffffffu, rs0, 1);
    rs0 += __shfl_xor_sync(0xffffffffu, rs0, 2);
    rs1 += __shfl_xor_sync(0xffffffffu, rs1, 1);
    rs1 += __shfl_xor_sync(0xffffffffu, rs1, 2);
    float i0 = 1.f / rs0, i1 = 1.f / rs1;
    if (tg == 0) { g_invl[r0] = i0; g_invl[r1] = i1; }
    #pragma unroll
    for (int n = 0; n < 16; ++n) {
        int colb = n * 8 + tg * 2;
        __stcs((float2*)(out_ctx + (size_t)r0 * 128 + colb),
               make_float2(ctxa[n * 4] * i0, ctxa[n * 4 + 1] * i0));
        __stcs((float2*)(out_ctx + (size_t)r1 * 128 + colb),
               make_float2(ctxa[n * 4 + 2] * i1, ctxa[n * 4 + 3] * i1));
    }
}

// ---- K4: fp16 scratch -> normalized fp32 attn + colsums (MLP=8 batched) ----
__global__ __launch_bounds__(256) void k_norm(float* __restrict__ attn) {
    __shared__ float invl_s[64];
    const int tid = threadIdx.x;
    const int rb = blockIdx.x * 64;
    if (tid < 64) invl_s[tid] = g_invl[rb + tid];
    __syncthreads();
    float cs[16];
    #pragma unroll
    for (int j = 0; j < 16; ++j) cs[j] = 0.f;
    #pragma unroll 1
    for (int r4 = 0; r4 < 64; r4 += 4) {
        // front-batch 8 independent 16B loads (4 rows x 2 positions)
        uint4 u[8];
        #pragma unroll
        for (int rr = 0; rr < 4; ++rr) {
            const uint4* src = (const uint4*)(g_eh + (size_t)(rb + r4 + rr) * 2048);
            u[rr * 2 + 0] = __ldcs(&src[tid]);
            u[rr * 2 + 1] = __ldcs(&src[tid + 256]);
        }
        #pragma unroll
        for (int rr = 0; rr < 4; ++rr) {
            float iv = invl_s[r4 + rr];
            float4* dst = (float4*)(attn + (size_t)(rb + r4 + rr) * 4096);
            #pragma unroll
            for (int j = 0; j < 2; ++j) {
                uint4 uu = u[rr * 2 + j];
                float2 f0 = __half22float2(*(__half2*)&uu.x);
                float2 f1 = __half22float2(*(__half2*)&uu.y);
                float2 f2 = __half22float2(*(__half2*)&uu.z);
                float2 f3 = __half22float2(*(__half2*)&uu.w);
                float4 v0 = make_float4(f0.x * iv, f0.y * iv, f1.x * iv, f1.y * iv);
                float4 v1 = make_float4(f2.x * iv, f2.y * iv, f3.x * iv, f3.y * iv);
                __stcs(&dst[(tid + j * 256) * 2 + 0], v0);
                __stcs(&dst[(tid + j * 256) * 2 + 1], v1);
                cs[j * 8 + 0] += v0.x; cs[j * 8 + 1] += v0.y;
                cs[j * 8 + 2] += v0.z; cs[j * 8 + 3] += v0.w;
                cs[j * 8 + 4] += v1.x; cs[j * 8 + 5] += v1.y;
                cs[j * 8 + 6] += v1.z; cs[j * 8 + 7] += v1.w;
            }
        }
    }
    #pragma unroll
    for (int j = 0; j < 2; ++j) {
        int c = (tid + j * 256) * 8;
        #pragma unroll
        for (int m = 0; m < 8; ++m)
            atomicAdd(&g_colsum[c + m], cs[j * 8 + m]);
    }
}

// ---- K5: usage EMA ----
__global__ void k_usage_copy(const float* __restrict__ ue, float* __restrict__ out) {
    int i = blockIdx.x * 256 + threadIdx.x;
    if (i < S_) out[i] = ue[i];
}
__global__ void k_usage_scatter(const float* __restrict__ ue,
                                const void* __restrict__ aidx,
                                float* __restrict__ out) {
    int i = blockIdx.x * 256 + threadIdx.x;
    if (i < NA_) {
        int mode = idx_mode(aidx);
        int idx = load_idx(aidx, i, mode);
        out[idx] = 0.95f * ue[idx] + 0.05f * (g_colsum[i] * (1.0f / 32768.0f));
    }
}

extern "C" void kernel_launch(void* const* d_in, const int* in_sizes, int n_in,
                              void* d_out, int out_size) {
    const float* hidden = (const float*)d_in[0];
    const float* kw     = (const float*)d_in[1];
    const float* skey   = (const float*)d_in[2];
    const float* sval   = (const float*)d_in[3];
    const float* uema   = (const float*)d_in[4];
    const void*  aidx   = d_in[5];

    float* out    = (float*)d_out;
    float* o_ctx  = out;
    float* o_attn = out + (size_t)4194304;
    float* o_q    = out + (size_t)138412032;
    float* o_use  = out + (size_t)140509184;

    cudaFuncSetAttribute(k_qproj,    cudaFuncAttributeMaxDynamicSharedMemorySize, QPROJ_SMEM);
    cudaFuncSetAttribute(k_attn_mma, cudaFuncAttributeMaxDynamicSharedMemorySize, MMA_SMEM);

    k_qproj<<<B_ / 64, 256, QPROJ_SMEM>>>(hidden, kw, o_q);
    k_prep<<<NA_, 64>>>(skey, sval, aidx);
    k_attn_mma<<<B_ / 128, 256, MMA_SMEM>>>(o_ctx);
    k_norm<<<B_ / 64, 256>>>(o_attn);
    k_usage_copy<<<(S_ + 255) / 256, 256>>>(uema, o_use);
    k_usage_scatter<<<(NA_ + 255) / 256, 256>>>(uema, aidx, o_use);
}

// round 15
// speedup vs baseline: 1.3214x; 1.0522x over previous
#include <cuda_runtime.h>
#include <cuda_fp16.h>
#include <math.h>
#include <stdint.h>

#define B_   32768
#define H_   256
#define DK_  64
#define DV_  128
#define S_   8192
#define NA_  4096

// ================= device scratch =================
__device__ float    g_qs  [(size_t)B_ * DK_];   // q * invnorm / TEMP
__device__ __half   g_kh  [(size_t)NA_ * DK_];  // k-hat hi   [slot][dk]
__device__ __half   g_kl  [(size_t)NA_ * DK_];  // k-hat lo residual
__device__ __half   g_vhT [(size_t)DV_ * NA_];  // V^T        [dv][slot]
__device__ uint32_t g_eh  [(size_t)B_ * 2048];  // unnorm exp(sims) as half2
__device__ float    g_invl[B_];
__device__ float    g_colsum[NA_];

__device__ __forceinline__ int idx_mode(const void* a) {
    const long long* a64 = (const long long*)a;
    long long v0 = a64[0], v1 = a64[1];
    return (v0 >= 0 && v0 < S_ && v1 >= 0 && v1 < S_) ? 1 : 0;
}
__device__ __forceinline__ int load_idx(const void* a, int i, int mode) {
    return mode ? (int)((const long long*)a)[i] : ((const int*)a)[i];
}

// FFMA-pipe exp: valid for |x| <= ~40, rel err ~1e-7. No MUFU.
__device__ __forceinline__ float fast_exp(float x) {
    float y = x * 1.4426950408889634f;
    float t = y + 12582912.0f;
    int   n = __float_as_int(t) - 0x4B400000;
    float f = y - (t - 12582912.0f);
    float p = 1.5403530e-4f;
    p = fmaf(p, f, 1.3333558e-3f);
    p = fmaf(p, f, 9.6181291e-3f);
    p = fmaf(p, f, 5.5504109e-2f);
    p = fmaf(p, f, 2.4022651e-1f);
    p = fmaf(p, f, 6.9314718e-1f);
    p = fmaf(p, f, 1.0f);
    return p * __int_as_float((n + 127) << 23);
}

__device__ __forceinline__ uint32_t smem_to_u32(const void* p) {
    uint32_t a;
    asm("{ .reg .u64 t; cvta.to.shared.u64 t, %1; cvt.u32.u64 %0, t; }" : "=r"(a) : "l"(p));
    return a;
}
__device__ __forceinline__ void cp16(uint32_t smem, const void* g) {
    asm volatile("cp.async.cg.shared.global [%0], [%1], 16;" :: "r"(smem), "l"(g));
}
__device__ __forceinline__ void ldsm4(uint32_t& r0, uint32_t& r1, uint32_t& r2,
                                      uint32_t& r3, uint32_t addr) {
    asm volatile("ldmatrix.sync.aligned.m8n8.x4.shared.b16 {%0,%1,%2,%3}, [%4];"
                 : "=r"(r0), "=r"(r1), "=r"(r2), "=r"(r3) : "r"(addr));
}

__device__ __forceinline__ uint32_t pack_split_h(float a, float b, uint32_t& lo) {
    __half2 hh = __floats2half2_rn(a, b);
    float2 hf = __half22float2(hh);
    __half2 ll = __floats2half2_rn(a - hf.x, b - hf.y);
    lo = *(uint32_t*)&ll;
    return *(uint32_t*)&hh;
}
__device__ __forceinline__ uint32_t pack_h(float a, float b) {
    __half2 hh = __floats2half2_rn(a, b);
    return *(uint32_t*)&hh;
}

__device__ __forceinline__ void mma16816(float* c, const uint32_t* a,
                                         uint32_t b0, uint32_t b1) {
    asm volatile("mma.sync.aligned.m16n8k16.row.col.f32.f16.f16.f32 "
                 "{%0,%1,%2,%3}, {%4,%5,%6,%7}, {%8,%9}, {%0,%1,%2,%3};"
                 : "+f"(c[0]), "+f"(c[1]), "+f"(c[2]), "+f"(c[3])
                 : "r"(a[0]), "r"(a[1]), "r"(a[2]), "r"(a[3]), "r"(b0), "r"(b1));
}

// ---- K1: query = hidden @ kw^T ; g_qs = q*invnorm/TEMP ----
#define QPROJ_SMEM ((16384 + 16384 + 64) * 4)
__global__ __launch_bounds__(256) void k_qproj(const float* __restrict__ hidden,
                                               const float* __restrict__ kw,
                                               float* __restrict__ out_q) {
    extern __shared__ float sm1[];
    float* hid_s = sm1;
    float* kwT   = sm1 + 16384;
    float* inv_s = sm1 + 32768;
    const int tid = threadIdx.x;
    const int rowbase = blockIdx.x * 64;
    #pragma unroll
    for (int i = 0; i < 16; ++i) {
        int id = tid + i * 256, r = id >> 6, c4 = id & 63;
        *(float4*)&hid_s[r * 256 + c4 * 4] =
            *(const float4*)&hidden[(size_t)(rowbase + r) * 256 + c4 * 4];
    }
    #pragma unroll
    for (int i = 0; i < 16; ++i) {
        int id = tid + i * 256, c = id & 63, k4 = id >> 6;
        float4 v = *(const float4*)&kw[(size_t)c * 256 + k4 * 4];
        kwT[(k4 * 4 + 0) * 64 + c] = v.x; kwT[(k4 * 4 + 1) * 64 + c] = v.y;
        kwT[(k4 * 4 + 2) * 64 + c] = v.z; kwT[(k4 * 4 + 3) * 64 + c] = v.w;
    }
    __syncthreads();
    const int tx = tid & 15, ty = tid >> 4;
    float acc[4][4] = {};
    #pragma unroll 4
    for (int k = 0; k < 256; ++k) {
        float4 b = *(float4*)&kwT[k * 64 + tx * 4];
        #pragma unroll
        for (int i = 0; i < 4; ++i) {
            float a = hid_s[(ty * 4 + i) * 256 + k];
            acc[i][0] += a * b.x; acc[i][1] += a * b.y;
            acc[i][2] += a * b.z; acc[i][3] += a * b.w;
        }
    }
    __syncthreads();
    float* q_s = hid_s;
    #pragma unroll
    for (int i = 0; i < 4; ++i)
        *(float4*)&q_s[(ty * 4 + i) * 68 + tx * 4] =
            make_float4(acc[i][0], acc[i][1], acc[i][2], acc[i][3]);
    __syncthreads();
    if (tid < 64) {
        float ss = 0.f;
        #pragma unroll
        for (int c4 = 0; c4 < 16; ++c4) {
            float4 v = *(float4*)&q_s[tid * 68 + c4 * 4];
            ss += v.x * v.x + v.y * v.y + v.z * v.z + v.w * v.w;
        }
        inv_s[tid] = 1.0f / fmaxf(sqrtf(ss), 1e-12f);
    }
    __syncthreads();
    #pragma unroll
    for (int i = 0; i < 4; ++i) {
        int r = ty * 4 + i;
        float4 v = make_float4(acc[i][0], acc[i][1], acc[i][2], acc[i][3]);
        *(float4*)&out_q[(size_t)(rowbase + r) * 64 + tx * 4] = v;
        float s = inv_s[r] * 10.0f;
        *(float4*)&g_qs[(size_t)(rowbase + r) * 64 + tx * 4] =
            make_float4(v.x * s, v.y * s, v.z * s, v.w * s);
    }
}

// ---- K2: normalize keys (fp16 split), transpose values (fp16) ----
__global__ __launch_bounds__(64) void k_prep(const float* __restrict__ slots_key,
                                             const float* __restrict__ slots_value,
                                             const void* __restrict__ active_idx) {
    const int i = blockIdx.x, t = threadIdx.x;
    const int mode = idx_mode(active_idx);
    const int idx = load_idx(active_idx, i, mode);
    float v = slots_key[(size_t)idx * DK_ + t];
    float ss = v * v;
    #pragma unroll
    for (int o = 16; o > 0; o >>= 1) ss += __shfl_down_sync(0xffffffffu, ss, o);
    __shared__ float sred[2];
    if ((t & 31) == 0) sred[t >> 5] = ss;
    __syncthreads();
    float inv = 1.0f / fmaxf(sqrtf(sred[0] + sred[1]), 1e-12f);
    float kn = v * inv;
    __half kh = __float2half_rn(kn);
    g_kh[(size_t)i * DK_ + t] = kh;
    g_kl[(size_t)i * DK_ + t] = __float2half_rn(kn - __half2float(kh));
    #pragma unroll
    for (int h = 0; h < 2; ++h) {
        int d = t + h * 64;
        g_vhT[(size_t)d * NA_ + i] = __float2half_rn(slots_value[(size_t)idx * DV_ + d]);
    }
    if (t == 0) g_colsum[i] = 0.f;
}

// ---- K3: HMMA fused attention (R7 core; q in smem via ldmatrix) ----
// [buf0 71680][buf1 71680][qh 18432][ql 18432] = 180224
#define BUF_SZ  71680
#define KL_OFF  18432
#define VH_OFF  36864
#define QH_OFF  143360
#define QL_OFF  161792
#define MMA_SMEM 180224

__global__ __launch_bounds__(256, 1) void k_attn_mma(float* __restrict__ out_ctx) {
    extern __shared__ char smc[];
    const uint32_t sbase = smem_to_u32(smc);
    const int tid  = threadIdx.x;
    const int wid  = tid >> 5, lane = tid & 31;
    const int g    = lane >> 2, tg = lane & 3;
    const int rowbase = blockIdx.x * 128;
    const int r0 = rowbase + wid * 16 + g;
    const int r1 = r0 + 8;

    auto load_tile = [&](int t, int b) {
        const int cb = t * 128;
        const uint32_t bb = sbase + b * BUF_SZ;
        #pragma unroll
        for (int i = 0; i < 4; ++i) {
            int id = tid + i * 256, row = id >> 3, c = id & 7;
            cp16(bb + row * 144 + c * 16, g_kh + (size_t)(cb + row) * 64 + c * 8);
        }
        #pragma unroll
        for (int i = 0; i < 4; ++i) {
            int id = tid + i * 256, row = id >> 3, c = id & 7;
            cp16(bb + KL_OFF + row * 144 + c * 16, g_kl + (size_t)(cb + row) * 64 + c * 8);
        }
        #pragma unroll
        for (int i = 0; i < 8; ++i) {
            int id = tid + i * 256, row = id >> 4, c = id & 15;
            cp16(bb + VH_OFF + row * 272 + c * 16, g_vhT + (size_t)row * NA_ + cb + c * 8);
        }
        asm volatile("cp.async.commit_group;" ::: "memory");
    };

    load_tile(0, 0);

    // stage q splits into smem (per-warp ldmatrix A layout, pitch 144B)
    {
        int row = tid >> 1;
        int cb32 = (tid & 1) * 16;              // half2-pair base (16 pairs each)
        int w = row >> 4, sr = row & 15;
        uint32_t qoff = (uint32_t)(w * 2304 + sr * 144 + cb32 * 4);
        const float* qp = g_qs + (size_t)(rowbase + row) * 64 + cb32 * 2;
        #pragma unroll
        for (int j = 0; j < 16; ++j) {
            float a = qp[2 * j], b = qp[2 * j + 1];
            uint32_t lo;
            uint32_t hi = pack_split_h(a, b, lo);
            *(uint32_t*)(smc + QH_OFF + qoff + j * 4) = hi;
            *(uint32_t*)(smc + QL_OFF + qoff + j * 4) = lo;
        }
    }
    __syncthreads();

    float ctxa[64];
    #pragma unroll
    for (int i = 0; i < 64; ++i) ctxa[i] = 0.f;
    float rs0 = 0.f, rs1 = 0.f;

    const uint32_t qa = sbase + QH_OFF + (uint32_t)(wid * 2304)
                      + (uint32_t)(lane & 15) * 144u + (uint32_t)(lane >> 4) * 16u;
    const char* kh_l0 = smc + (size_t)(g * 144 + tg * 4);
    const char* kl_l0 = smc + (size_t)(KL_OFF + g * 144 + tg * 4);
    const char* vh_l0 = smc + (size_t)(VH_OFF + g * 272 + tg * 4);

    #pragma unroll 1
    for (int t = 0; t < 32; ++t) {
        const int cb = t * 128;
        __syncthreads();
        if (t < 31) load_tile(t + 1, (t + 1) & 1);
        if (t < 31) asm volatile("cp.async.wait_group 1;" ::: "memory");
        else        asm volatile("cp.async.wait_group 0;" ::: "memory");
        __syncthreads();

        const size_t boff = (size_t)(t & 1) * BUF_SZ;
        const char* kh_l = kh_l0 + boff;
        const char* kl_l = kl_l0 + boff;
        const char* vh_l = vh_l0 + boff;

        // reload q A-fragments from smem (transient registers)
        uint32_t qh[4][4], ql[4][4];
        #pragma unroll
        for (int kk = 0; kk < 4; ++kk) {
            ldsm4(qh[kk][0], qh[kk][1], qh[kk][2], qh[kk][3], qa + kk * 32);
            ldsm4(ql[kk][0], ql[kk][1], ql[kk][2], ql[kk][3],
                  qa + (QL_OFF - QH_OFF) + kk * 32);
        }

        // sims: qh*kh + ql*kh + qh*kl, 3 independent chains
        uint32_t ph[8][4];
        #pragma unroll
        for (int n = 0; n < 16; ++n) {
            float ccA[4] = {0.f, 0.f, 0.f, 0.f};
            float ccB[4] = {0.f, 0.f, 0.f, 0.f};
            float ccC[4] = {0.f, 0.f, 0.f, 0.f};
            const char* kh_n = kh_l + n * (8 * 144);
            const char* kl_n = kl_l + n * (8 * 144);
            #pragma unroll
            for (int kk = 0; kk < 4; ++kk) {
                uint32_t bh0 = *(const uint32_t*)(kh_n + kk * 32);
                uint32_t bh1 = *(const uint32_t*)(kh_n + kk * 32 + 16);
                uint32_t bl0 = *(const uint32_t*)(kl_n + kk * 32);
                uint32_t bl1 = *(const uint32_t*)(kl_n + kk * 32 + 16);
                mma16816(ccA, qh[kk], bh0, bh1);
                mma16816(ccB, ql[kk], bh0, bh1);
                mma16816(ccC, qh[kk], bl0, bl1);
            }
            float e0 = fast_exp(ccA[0] + ccB[0] + ccC[0]);
            float e1 = fast_exp(ccA[1] + ccB[1] + ccC[1]);
            float e2 = fast_exp(ccA[2] + ccB[2] + ccC[2]);
            float e3 = fast_exp(ccA[3] + ccB[3] + ccC[3]);
            rs0 += e0 + e1; rs1 += e2 + e3;
            int j = n >> 1, h = (n & 1) * 2;
            uint32_t p01 = pack_h(e0, e1);
            uint32_t p23 = pack_h(e2, e3);
            ph[j][h]     = p01;
            ph[j][h + 1] = p23;
            int cidx = (cb >> 1) + n * 4 + tg;
            g_eh[(size_t)r0 * 2048 + cidx] = p01;
            g_eh[(size_t)r1 * 2048 + cidx] = p23;
        }

        // ctx: ph * vh, kk-outer for 16 independent chains
        #pragma unroll
        for (int kk = 0; kk < 8; ++kk) {
            const char* vh_k = vh_l + kk * 32;
            #pragma unroll
            for (int n = 0; n < 16; ++n) {
                uint32_t bh0 = *(const uint32_t*)(vh_k + n * (8 * 272));
                uint32_t bh1 = *(const uint32_t*)(vh_k + n * (8 * 272) + 16);
                mma16816(ctxa + n * 4, ph[kk], bh0, bh1);
            }
        }
    }

    rs0 += __shfl_xor_sync(0xffffffffu, rs0, 1);
    rs0 += __shfl_xor_sync(0xffffffffu, rs0, 2);
    rs1 += __shfl_xor_sync(0xffffffffu, rs1, 1);
    rs1 += __shfl_xor_sync(0xffffffffu, rs1, 2);
    float i0 = 1.f / rs0, i1 = 1.f / rs1;
    if (tg == 0) { g_invl[r0] = i0; g_invl[r1] = i1; }
    #pragma unroll
    for (int n = 0; n < 16; ++n) {
        int colb = n * 8 + tg * 2;
        __stcs((float2*)(out_ctx + (size_t)r0 * 128 + colb),
               make_float2(ctxa[n * 4] * i0, ctxa[n * 4 + 1] * i0));
        __stcs((float2*)(out_ctx + (size_t)r1 * 128 + colb),
               make_float2(ctxa[n * 4 + 2] * i1, ctxa[n * 4 + 3] * i1));
    }
}

// ---- K4: fp16 scratch -> normalized fp32 attn + colsums (MLP=16 batched) ----
__global__ __launch_bounds__(256) void k_norm(float* __restrict__ attn) {
    __shared__ float invl_s[64];
    const int tid = threadIdx.x;
    const int rb = blockIdx.x * 64;
    if (tid < 64) invl_s[tid] = g_invl[rb + tid];
    __syncthreads();
    float cs[16];
    #pragma unroll
    for (int j = 0; j < 16; ++j) cs[j] = 0.f;
    #pragma unroll 1
    for (int r8 = 0; r8 < 64; r8 += 8) {
        // front-batch 16 independent 16B loads (8 rows x 2 positions)
        uint4 u[16];
        #pragma unroll
        for (int rr = 0; rr < 8; ++rr) {
            const uint4* src = (const uint4*)(g_eh + (size_t)(rb + r8 + rr) * 2048);
            u[rr * 2 + 0] = __ldcs(&src[tid]);
            u[rr * 2 + 1] = __ldcs(&src[tid + 256]);
        }
        #pragma unroll
        for (int rr = 0; rr < 8; ++rr) {
            float iv = invl_s[r8 + rr];
            float4* dst = (float4*)(attn + (size_t)(rb + r8 + rr) * 4096);
            #pragma unroll
            for (int j = 0; j < 2; ++j) {
                uint4 uu = u[rr * 2 + j];
                float2 f0 = __half22float2(*(__half2*)&uu.x);
                float2 f1 = __half22float2(*(__half2*)&uu.y);
                float2 f2 = __half22float2(*(__half2*)&uu.z);
                float2 f3 = __half22float2(*(__half2*)&uu.w);
                float4 v0 = make_float4(f0.x * iv, f0.y * iv, f1.x * iv, f1.y * iv);
                float4 v1 = make_float4(f2.x * iv, f2.y * iv, f3.x * iv, f3.y * iv);
                __stcs(&dst[(tid + j * 256) * 2 + 0], v0);
                __stcs(&dst[(tid + j * 256) * 2 + 1], v1);
                cs[j * 8 + 0] += v0.x; cs[j * 8 + 1] += v0.y;
                cs[j * 8 + 2] += v0.z; cs[j * 8 + 3] += v0.w;
                cs[j * 8 + 4] += v1.x; cs[j * 8 + 5] += v1.y;
                cs[j * 8 + 6] += v1.z; cs[j * 8 + 7] += v1.w;
            }
        }
    }
    #pragma unroll
    for (int j = 0; j < 2; ++j) {
        int c = (tid + j * 256) * 8;
        #pragma unroll
        for (int m = 0; m < 8; ++m)
            atomicAdd(&g_colsum[c + m], cs[j * 8 + m]);
    }
}

// ---- K5: usage EMA ----
__global__ void k_usage_copy(const float* __restrict__ ue, float* __restrict__ out) {
    int i = blockIdx.x * 256 + threadIdx.x;
    if (i < S_) out[i] = ue[i];
}
__global__ void k_usage_scatter(const float* __restrict__ ue,
                                const void* __restrict__ aidx,
                                float* __restrict__ out) {
    int i = blockIdx.x * 256 + threadIdx.x;
    if (i < NA_) {
        int mode = idx_mode(aidx);
        int idx = load_idx(aidx, i, mode);
        out[idx] = 0.95f * ue[idx] + 0.05f * (g_colsum[i] * (1.0f / 32768.0f));
    }
}

extern "C" void kernel_launch(void* const* d_in, const int* in_sizes, int n_in,
                              void* d_out, int out_size) {
    const float* hidden = (const float*)d_in[0];
    const float* kw     = (const float*)d_in[1];
    const float* skey   = (const float*)d_in[2];
    const float* sval   = (const float*)d_in[3];
    const float* uema   = (const float*)d_in[4];
    const void*  aidx   = d_in[5];

    float* out    = (float*)d_out;
    float* o_ctx  = out;
    float* o_attn = out + (size_t)4194304;
    float* o_q    = out + (size_t)138412032;
    float* o_use  = out + (size_t)140509184;

    cudaFuncSetAttribute(k_qproj,    cudaFuncAttributeMaxDynamicSharedMemorySize, QPROJ_SMEM);
    cudaFuncSetAttribute(k_attn_mma, cudaFuncAttributeMaxDynamicSharedMemorySize, MMA_SMEM);

    k_qproj<<<B_ / 64, 256, QPROJ_SMEM>>>(hidden, kw, o_q);
    k_prep<<<NA_, 64>>>(skey, sval, aidx);
    k_attn_mma<<<B_ / 128, 256, MMA_SMEM>>>(o_ctx);
    k_norm<<<B_ / 64, 256>>>(o_attn);
    k_usage_copy<<<(S_ + 255) / 256, 256>>>(uema, o_use);
    k_usage_scatter<<<(NA_ + 255) / 256, 256>>>(uema, aidx, o_use);
}